// round 15
// baseline (speedup 1.0000x reference)
#include <cuda_runtime.h>
#include <cmath>

// Problem constants
#define B_    4096
#define IN_   1024
#define F_    512
#define HID_  128
#define D_    128
#define RH_   64
#define C_    10
#define R_    16
#define CH_   1280   // C_*HID_
#define NSEG_ 8
#define CHSEG_ 160   // CH_/NSEG_
#define STG_  5      // cp.async pipeline stages
#define KW_SMEM_ ((2560 + STG_ * 4096) * 4)   // 92160 bytes
// k_out v7: 2x sx[16][257] + 2x swt[256*16] + sp[32*16*17]
#define KO_SMEM_ ((2 * 16 * 257 + 2 * 256 * 16 + 32 * 16 * 17) * 4)  // 101504 bytes

// ---------------- device scratch ----------------
__device__ __align__(256) float g_rv[R_][D_];
__device__ __align__(256) float g_P[CH_][R_];            // P[ch][r] = w[r,c]*W2[r,h]
__device__ __align__(256) float g_WeffP[NSEG_][R_][F_];  // k_weff partials (incl. bias)
__device__ __align__(256) float g_WxT[IN_][R_];          // [i][r], atomic-accumulated
__device__ __align__(256) float g_cst[R_];               // beff + Weff·base_b (atomics)

// ---------------- helpers ----------------
__device__ __forceinline__ unsigned long long pk2(float a, float b) {
    unsigned long long r;
    asm("mov.b64 %0, {%1,%2};" : "=l"(r) : "f"(a), "f"(b));
    return r;
}
__device__ __forceinline__ void upk2(unsigned long long v, float& a, float& b) {
    asm("mov.b64 {%0,%1}, %2;" : "=f"(a), "=f"(b) : "l"(v));
}
#define FMA2(acc, a, b) asm("fma.rn.f32x2 %0, %1, %2, %0;" : "+l"(acc) : "l"(a), "l"(b))

__device__ __forceinline__ unsigned smem_u32(const void* p) {
    return (unsigned)__cvta_generic_to_shared(p);
}
__device__ __forceinline__ void cp16(unsigned dst, const void* src) {
    asm volatile("cp.async.cg.shared.global [%0], [%1], 16;" :: "r"(dst), "l"(src) : "memory");
}

// ============ k_head: fused w, r1, rv, W2, b1, beff->cst, P; zero WxT ============
__global__ void __launch_bounds__(256) k_head(
    const float* __restrict__ pref,
    const float* __restrict__ wm1_w, const float* __restrict__ wm1_b,
    const float* __restrict__ wm2_w, const float* __restrict__ wm2_b,
    const float* __restrict__ ray0_w, const float* __restrict__ ray0_b,
    const float* __restrict__ ray2_w, const float* __restrict__ ray2_b,
    const float* __restrict__ fc2_w, const float* __restrict__ fc2_b,
    const float* __restrict__ b1_w,  const float* __restrict__ b1_b,
    const float* __restrict__ b2_w,  const float* __restrict__ b2_b) {
    int r = blockIdx.x;
    int t = threadIdx.x;
    int warp = t >> 5, lane = t & 31;
    __shared__ float sh[16];
    __shared__ float sw[C_];
    __shared__ float sinv;
    __shared__ float sr1[RH_];
    __shared__ __align__(16) float srv[D_];
    __shared__ __align__(16) float sW2[HID_];
    __shared__ __align__(16) float sb1[HID_];
    __shared__ float sb0[HID_], sbb[HID_], sb2r[D_];

    // zero g_WxT for this call (graph replay safe)
    for (int z = r * 256 + t; z < IN_ * R_; z += 16 * 256)
        ((float*)g_WxT)[z] = 0.f;

    float p0 = __ldg(pref + 2 * r), p1 = __ldg(pref + 2 * r + 1);
    if (t < 16) {
        float a = p0 * __ldg(wm1_w + t * 2) + p1 * __ldg(wm1_w + t * 2 + 1) + __ldg(wm1_b + t);
        sh[t] = a > 0.f ? a : 0.f;
    }
    __syncthreads();
    if (t < C_) {
        float a = __ldg(wm2_b + t);
        #pragma unroll
        for (int j = 0; j < 16; j++) a += sh[j] * __ldg(wm2_w + t * 16 + j);
        sw[t] = 1.f / (1.f + expf(-a));
    }
    __syncthreads();
    if (t == 0) {
        float s = 0.f;
        #pragma unroll
        for (int c = 0; c < C_; c++) s += sw[c];
        sinv = 1.f / s;
    }
    __syncthreads();
    if (t < C_) sw[t] *= sinv;
    __syncthreads();

    if (t < RH_) {
        float a = 0.f;
        #pragma unroll
        for (int c = 0; c < C_; c++) {
            float2 rw = __ldg((const float2*)(ray0_w + (c * RH_ + t) * 2));
            a += sw[c] * (p0 * rw.x + p1 * rw.y + __ldg(ray0_b + c * RH_ + t));
        }
        sr1[t] = a > 0.f ? a : 0.f;
    } else if (t < 64 + D_) {
        int d = t - 64;
        float b = 0.f;
        #pragma unroll
        for (int c = 0; c < C_; c++) b += sw[c] * __ldg(ray2_b + c * D_ + d);
        sb2r[d] = b;
    }
    __syncthreads();

    // rv: 8 warps x 16 oi, lanes over h
    {
        float r1a = sr1[lane], r1b = sr1[lane + 32];
        float acc[16];
        #pragma unroll
        for (int oi = 0; oi < 16; oi++) acc[oi] = 0.f;
        #pragma unroll
        for (int c = 0; c < C_; c++) {
            float wc = sw[c];
            #pragma unroll
            for (int oi = 0; oi < 16; oi++) {
                int o = warp * 16 + oi;
                const float* row = ray2_w + ((size_t)(c * D_ + o)) * RH_;
                acc[oi] += wc * (__ldg(row + lane) * r1a + __ldg(row + lane + 32) * r1b);
            }
        }
        #pragma unroll
        for (int oi = 0; oi < 16; oi++) {
            float s = acc[oi];
            #pragma unroll
            for (int off = 16; off > 0; off >>= 1) s += __shfl_down_sync(0xffffffffu, s, off);
            if (lane == 0) {
                int o = warp * 16 + oi;
                float v = s + sb2r[o];
                srv[o] = v;
                g_rv[r][o] = v;
            }
        }
    }
    if (t < 128) {
        float b = 0.f;
        #pragma unroll
        for (int c = 0; c < C_; c++) b += sw[c] * __ldg(fc2_b + c * HID_ + t);
        sb0[t] = b;
    } else {
        int o = t - 128;
        float b = 0.f;
        #pragma unroll
        for (int c = 0; c < C_; c++) b += sw[c] * __ldg(b1_b + c * HID_ + o);
        sbb[o] = b;
    }
    __syncthreads();

    // W2 (warps 0-3) and b1 (warps 4-7): warp handles 32 o's
    {
        int kind = warp >> 2;
        int ob = (warp & 3) * 32;
        const float* Wc = kind ? b1_w : fc2_w;
        float4 rv4 = *(const float4*)&srv[lane * 4];
        float acc[32];
        #pragma unroll
        for (int oi = 0; oi < 32; oi++) acc[oi] = 0.f;
        #pragma unroll
        for (int c = 0; c < C_; c++) {
            float wc = sw[c];
            #pragma unroll
            for (int oi = 0; oi < 32; oi++) {
                int o = ob + oi;
                float4 v = __ldg((const float4*)(Wc + ((size_t)(c * HID_ + o)) * D_) + lane);
                acc[oi] += wc * (v.x * rv4.x + v.y * rv4.y + v.z * rv4.z + v.w * rv4.w);
            }
        }
        #pragma unroll
        for (int oi = 0; oi < 32; oi++) {
            float s = acc[oi];
            #pragma unroll
            for (int off = 16; off > 0; off >>= 1) s += __shfl_down_sync(0xffffffffu, s, off);
            if (lane == 0) {
                int o = ob + oi;
                if (kind) sb1[o] = s + sbb[o]; else sW2[o] = s + sb0[o];
            }
        }
    }
    __syncthreads();

    if (warp == 0) {
        float4 rv4 = *(const float4*)&srv[lane * 4];
        float acc = 0.f;
        #pragma unroll
        for (int c = 0; c < C_; c++) {
            float wc = sw[c];
            float4 bw = __ldg((const float4*)(b2_w + c * D_) + lane);
            acc += wc * (bw.x * rv4.x + bw.y * rv4.y + bw.z * rv4.z + bw.w * rv4.w);
            if (lane == 0) acc += wc * __ldg(b2_b + c);
        }
        float4 w24 = *(const float4*)&sW2[lane * 4];
        float4 b14 = *(const float4*)&sb1[lane * 4];
        acc += w24.x * b14.x + w24.y * b14.y + w24.z * b14.z + w24.w * b14.w;
        #pragma unroll
        for (int off = 16; off > 0; off >>= 1) acc += __shfl_down_sync(0xffffffffu, acc, off);
        if (lane == 0) g_cst[r] = acc;   // beff; k_wx atomically adds Weff·base_b
    }
    for (int ch = t; ch < CH_; ch += 256)
        g_P[ch][r] = sw[ch >> 7] * sW2[ch & 127];
}

// ============ k_weff v7: cp.async pipeline, strength-reduced addressing ========
extern __shared__ float dsm_[];
__global__ void __launch_bounds__(256, 2) k_weff(const float* __restrict__ fc1_w,
                                                 const float* __restrict__ fc1_b) {
    float* sP   = dsm_;          // 2560 floats (160 ch x 16 r)
    float* sbuf = dsm_ + 2560;   // STG_ x 4096 floats (4 ch x 8 f x 128 d)
    int seg = blockIdx.y;
    int t = threadIdx.x;
    int warp = t >> 5, lane = t & 31;

    for (int idx = t; idx < CHSEG_ * 16; idx += 256)
        sP[idx] = ((const float*)g_P[seg * CHSEG_])[idx];

    const float4* gbase = (const float4*)fc1_w
        + (size_t)(seg * CHSEG_) * 16384u + (size_t)(blockIdx.x * 8 + warp) * 32u + lane;
    unsigned dstbase = smem_u32(sbuf) + (unsigned)((warp * 32 + lane) * 16);
    const float4* myb = (const float4*)sbuf + (warp * 32 + lane);  // + slot*1024 + q*256

    __syncthreads();   // sP visible to all warps (the ONLY cross-warp data)

    #pragma unroll
    for (int s = 0; s < STG_ - 1; s++) {
        #pragma unroll
        for (int q = 0; q < 4; q++)
            cp16(dstbase + (unsigned)(s * 16384 + q * 4096),
                 gbase + (size_t)(s * 4 + q) * 16384u);
        asm volatile("cp.async.commit_group;" ::: "memory");
    }

    unsigned long long acc[4][8];
    #pragma unroll
    for (int j = 0; j < 4; j++)
        #pragma unroll
        for (int rp = 0; rp < 8; rp++) acc[j][rp] = 0ull;

    const float4* gpre = gbase + (size_t)(STG_ - 1) * 4 * 16384u;
    const ulonglong2* pPtr = (const ulonglong2*)sP;

    #pragma unroll 1
    for (int g = 0; g < (CHSEG_ / 4) / STG_; g++) {   // 8 outer groups
        #pragma unroll
        for (int j5 = 0; j5 < STG_; j5++) {           // slot = j5 (compile-time)
            int i = g * STG_ + j5;
            asm volatile("cp.async.wait_group %0;" :: "n"(STG_ - 2) : "memory");
            const float4* bq = myb + j5 * 1024;
            #pragma unroll
            for (int q = 0; q < 4; q++) {
                float4 v = bq[q * 256];
                ulonglong2 pA = pPtr[q * 4 + 0], pB = pPtr[q * 4 + 1];
                ulonglong2 pC = pPtr[q * 4 + 2], pD = pPtr[q * 4 + 3];
                unsigned long long u0 = pk2(v.x, v.x);
                unsigned long long u1 = pk2(v.y, v.y);
                unsigned long long u2 = pk2(v.z, v.z);
                unsigned long long u3 = pk2(v.w, v.w);
                FMA2(acc[0][0], u0, pA.x); FMA2(acc[0][1], u0, pA.y);
                FMA2(acc[0][2], u0, pB.x); FMA2(acc[0][3], u0, pB.y);
                FMA2(acc[0][4], u0, pC.x); FMA2(acc[0][5], u0, pC.y);
                FMA2(acc[0][6], u0, pD.x); FMA2(acc[0][7], u0, pD.y);
                FMA2(acc[1][0], u1, pA.x); FMA2(acc[1][1], u1, pA.y);
                FMA2(acc[1][2], u1, pB.x); FMA2(acc[1][3], u1, pB.y);
                FMA2(acc[1][4], u1, pC.x); FMA2(acc[1][5], u1, pC.y);
                FMA2(acc[1][6], u1, pD.x); FMA2(acc[1][7], u1, pD.y);
                FMA2(acc[2][0], u2, pA.x); FMA2(acc[2][1], u2, pA.y);
                FMA2(acc[2][2], u2, pB.x); FMA2(acc[2][3], u2, pB.y);
                FMA2(acc[2][4], u2, pC.x); FMA2(acc[2][5], u2, pC.y);
                FMA2(acc[2][6], u2, pD.x); FMA2(acc[2][7], u2, pD.y);
                FMA2(acc[3][0], u3, pA.x); FMA2(acc[3][1], u3, pA.y);
                FMA2(acc[3][2], u3, pB.x); FMA2(acc[3][3], u3, pB.y);
                FMA2(acc[3][4], u3, pC.x); FMA2(acc[3][5], u3, pC.y);
                FMA2(acc[3][6], u3, pD.x); FMA2(acc[3][7], u3, pD.y);
            }
            pPtr += 16;
            if (i < (CHSEG_ / 4) - (STG_ - 1)) {
                const unsigned pslot = (unsigned)(((j5 + STG_ - 1) % STG_) * 16384);
                #pragma unroll
                for (int q = 0; q < 4; q++)
                    cp16(dstbase + pslot + (unsigned)(q * 4096), gpre + q * 16384);
            }
            gpre += 65536;
            asm volatile("cp.async.commit_group;" ::: "memory");
        }
    }
    asm volatile("cp.async.wait_group 0;" ::: "memory");

    // fused fc1_b bias: lane covers ch = lane, lane+32, ... (5 iters)
    int f = blockIdx.x * 8 + warp;
    unsigned long long bacc[8];
    #pragma unroll
    for (int rp = 0; rp < 8; rp++) bacc[rp] = 0ull;
    #pragma unroll
    for (int it = 0; it < CHSEG_ / 32; it++) {
        int chl = it * 32 + lane;
        float bv = __ldg(fc1_b + (size_t)(seg * CHSEG_ + chl) * 512u + f);
        unsigned long long vv = pk2(bv, bv);
        const ulonglong2* pp = (const ulonglong2*)(sP + chl * 16);
        ulonglong2 pA = pp[0], pB = pp[1], pC = pp[2], pD = pp[3];
        FMA2(bacc[0], vv, pA.x); FMA2(bacc[1], vv, pA.y);
        FMA2(bacc[2], vv, pB.x); FMA2(bacc[3], vv, pB.y);
        FMA2(bacc[4], vv, pC.x); FMA2(bacc[5], vv, pC.y);
        FMA2(bacc[6], vv, pD.x); FMA2(bacc[7], vv, pD.y);
    }

    int d0 = lane * 4;
    float accr[16];
    #pragma unroll
    for (int rp = 0; rp < 8; rp++) {
        float a0, a1; upk2(bacc[rp], a0, a1);
        accr[2 * rp] = a0; accr[2 * rp + 1] = a1;
    }
    #pragma unroll
    for (int j = 0; j < 4; j++) {
        #pragma unroll
        for (int rp = 0; rp < 8; rp++) {
            float a0, a1; upk2(acc[j][rp], a0, a1);
            accr[2 * rp]     += a0 * g_rv[2 * rp][d0 + j];
            accr[2 * rp + 1] += a1 * g_rv[2 * rp + 1][d0 + j];
        }
    }
    #pragma unroll
    for (int off = 16; off > 0; off >>= 1)
        #pragma unroll
        for (int r = 0; r < 16; r++)
            accr[r] += __shfl_down_sync(0xffffffffu, accr[r], off);
    if (lane == 0) {
        #pragma unroll
        for (int r = 0; r < 16; r++) g_WeffP[seg][r][f] = accr[r];
    }
}

// ============ k_wx: sum 8 planes -> fold base_w -> atomic Wx; cst inline ======
__global__ void __launch_bounds__(128) k_wx(const float* __restrict__ base_w,
                                            const float* __restrict__ base_b) {
    __shared__ __align__(16) float sW[32][16];
    int t = threadIdx.x;
    int f0 = blockIdx.y * 32;
    for (int idx = t; idx < 32 * 16; idx += 128) {
        int ff = idx >> 4, r = idx & 15;
        float s = 0.f;
        #pragma unroll
        for (int sg = 0; sg < NSEG_; sg++) s += g_WeffP[sg][r][f0 + ff];
        sW[ff][r] = s;
    }
    __syncthreads();
    if (blockIdx.x == 0) {
        int r = t >> 3, fq = (t & 7) * 4;
        float p = 0.f;
        #pragma unroll
        for (int j = 0; j < 4; j++) p += sW[fq + j][r] * __ldg(base_b + f0 + fq + j);
        atomicAdd(&g_cst[r], p);
    }
    int i = blockIdx.x * 128 + t;
    unsigned long long acc[8];
    #pragma unroll
    for (int rp = 0; rp < 8; rp++) acc[rp] = 0ull;
    #pragma unroll 4
    for (int ff = 0; ff < 32; ff++) {
        float bw = __ldg(base_w + (size_t)(f0 + ff) * IN_ + i);
        unsigned long long b2 = pk2(bw, bw);
        const unsigned long long* pw = (const unsigned long long*)sW[ff];
        #pragma unroll
        for (int rp = 0; rp < 8; rp++) {
            unsigned long long tt = pw[rp];
            FMA2(acc[rp], b2, tt);
        }
    }
    #pragma unroll
    for (int rp = 0; rp < 8; rp++) {
        float a, b; upk2(acc[rp], a, b);
        atomicAdd(&g_WxT[i][2 * rp], a);
        atomicAdd(&g_WxT[i][2 * rp + 1], b);
    }
}

// ============ k_out v7: 512 thr, double-buffered sx/swt, 1 sync per chunk =====
extern __shared__ float osm_[];
__global__ void __launch_bounds__(512) k_out(const float* __restrict__ x,
                                             float* __restrict__ out, int write_raw) {
    float* sxa  = osm_;                         // [16][257]
    float* sxb  = sxa + 16 * 257;
    float* swta = sxb + 16 * 257;               // [256*16]
    float* swtb = swta + 256 * 16;
    float* sp   = swtb + 256 * 16;              // [32*16*17]
    int t = threadIdx.x;
    int bl = t & 15, part = t >> 4;             // 32 parts
    int bbase = blockIdx.x * 16;

    // per-thread staging coords (computed once)
    int sb = t >> 8, si = t & 255;              // x staging: 2 rows per pass of 512
    const float* xrow0 = x + (size_t)(bbase + sb) * IN_ + si;          // rows sb, sb+2, ...
    const float4* wsrc = (const float4*)g_WxT + t;                     // +512 per k

    // stage chunk 0
    #pragma unroll
    for (int k = 0; k < 8; k++)
        sxa[(sb + 2 * k) * 257 + si] = __ldg(xrow0 + (size_t)(2 * k) * IN_);
    #pragma unroll
    for (int k = 0; k < 2; k++)
        ((float4*)swta)[k * 512 + t] = __ldg(wsrc + k * 512);
    __syncthreads();

    unsigned long long acc[8];
    #pragma unroll
    for (int rp = 0; rp < 8; rp++) acc[rp] = 0ull;

    #pragma unroll
    for (int c = 0; c < 4; c++) {
        const float* cx = (c & 1) ? sxb : sxa;
        const float* cw = (c & 1) ? swtb : swta;
        if (c < 3) {
            float* nx = (c & 1) ? sxa : sxb;
            float* nw = (c & 1) ? swta : swtb;
            const float* xs = xrow0 + (c + 1) * 256;
            #pragma unroll
            for (int k = 0; k < 8; k++)
                nx[(sb + 2 * k) * 257 + si] = __ldg(xs + (size_t)(2 * k) * IN_);
            const float4* ws = wsrc + (c + 1) * 1024;
            #pragma unroll
            for (int k = 0; k < 2; k++)
                ((float4*)nw)[k * 512 + t] = __ldg(ws + k * 512);
        }
        const float* xp = cx + bl * 257 + part * 8;
        const ulonglong2* wp = (const ulonglong2*)(cw + part * 128);
        #pragma unroll
        for (int ii = 0; ii < 8; ii++) {
            float xv = xp[ii];
            unsigned long long ux = pk2(xv, xv);
            ulonglong2 wA = wp[0], wB = wp[1], wC = wp[2], wD = wp[3];
            wp += 4;
            FMA2(acc[0], ux, wA.x); FMA2(acc[1], ux, wA.y);
            FMA2(acc[2], ux, wB.x); FMA2(acc[3], ux, wB.y);
            FMA2(acc[4], ux, wC.x); FMA2(acc[5], ux, wC.y);
            FMA2(acc[6], ux, wD.x); FMA2(acc[7], ux, wD.y);
        }
        __syncthreads();
    }

    float* myp = sp + (size_t)(part * 16 + bl) * 17;
    #pragma unroll
    for (int rp = 0; rp < 8; rp++) {
        float a, b; upk2(acc[rp], a, b);
        myp[2 * rp] = a;
        myp[2 * rp + 1] = b;
    }
    __syncthreads();

    if (t < 256) {
        int r = t >> 4, b = t & 15;
        float s = 0.f;
        #pragma unroll
        for (int p = 0; p < 32; p++) s += sp[(size_t)(p * 16 + b) * 17 + r];
        float v = s + g_cst[r];
        out[r * B_ + bbase + b] = 1.f / (1.f + expf(-v));
        if (write_raw) out[R_ * B_ + r * B_ + bbase + b] = v;
    }
}

// ---------------- launcher ----------------
extern "C" void kernel_launch(void* const* d_in, const int* in_sizes, int n_in,
                              void* d_out, int out_size) {
    const float* x      = (const float*)d_in[0];
    const float* pref   = (const float*)d_in[1];
    const float* base_w = (const float*)d_in[2];
    const float* base_b = (const float*)d_in[3];
    const float* wm1_w  = (const float*)d_in[4];
    const float* wm1_b  = (const float*)d_in[5];
    const float* wm2_w  = (const float*)d_in[6];
    const float* wm2_b  = (const float*)d_in[7];
    const float* ray0_w = (const float*)d_in[8];
    const float* ray0_b = (const float*)d_in[9];
    const float* ray2_w = (const float*)d_in[10];
    const float* ray2_b = (const float*)d_in[11];
    const float* fc1_w  = (const float*)d_in[12];
    const float* fc1_b  = (const float*)d_in[13];
    const float* b1_w   = (const float*)d_in[14];
    const float* b1_b   = (const float*)d_in[15];
    const float* fc2_w  = (const float*)d_in[16];
    const float* fc2_b  = (const float*)d_in[17];
    const float* b2_w   = (const float*)d_in[18];
    const float* b2_b   = (const float*)d_in[19];
    float* out = (float*)d_out;
    int write_raw = (out_size >= 2 * R_ * B_) ? 1 : 0;

    cudaFuncSetAttribute(k_weff, cudaFuncAttributeMaxDynamicSharedMemorySize, KW_SMEM_);
    cudaFuncSetAttribute(k_out, cudaFuncAttributeMaxDynamicSharedMemorySize, KO_SMEM_);

    k_head<<<R_, 256>>>(pref, wm1_w, wm1_b, wm2_w, wm2_b,
                        ray0_w, ray0_b, ray2_w, ray2_b,
                        fc2_w, fc2_b, b1_w, b1_b, b2_w, b2_b);
    k_weff<<<dim3(F_ / 8, NSEG_), 256, KW_SMEM_>>>(fc1_w, fc1_b);
    k_wx<<<dim3(8, 16), 128>>>(base_w, base_b);
    k_out<<<B_ / 16, 512, KO_SMEM_>>>(x, out, write_raw);   // #4 -> profiled
}

// round 16
// speedup vs baseline: 1.1325x; 1.1325x over previous
#include <cuda_runtime.h>
#include <cmath>

// Problem constants
#define B_    4096
#define IN_   1024
#define F_    512
#define HID_  128
#define D_    128
#define RH_   64
#define C_    10
#define R_    16
#define CH_   1280   // C_*HID_
#define NSEG_ 8
#define CHSEG_ 160   // CH_/NSEG_
#define STG_  5      // cp.async pipeline stages
#define KW_SMEM_ ((2560 + STG_ * 4096) * 4)   // 92160 bytes
#define KO_SMEM_ ((2 * 16 * 257 + 2 * 256 * 16 + 32 * 16 * 17) * 4)  // 101504 bytes

// ---------------- device scratch ----------------
__device__ __align__(256) float g_w[R_][C_];
__device__ __align__(256) float g_rv[R_][D_];
__device__ __align__(256) float g_W2[R_][HID_];
__device__ __align__(256) float g_b1[R_][HID_];
__device__ __align__(256) float g_beff[R_];
__device__ __align__(256) float g_P[CH_][R_];            // P[ch][r] = w[r,c]*W2[r,h]
__device__ __align__(256) float g_WeffP[NSEG_][R_][F_];  // k_weff partials (incl. bias)
__device__ __align__(256) float g_WxT[IN_][R_];          // [i][r], atomic-accumulated
__device__ __align__(256) float g_cst[R_];               // Weff·base_b (atomics)

// ---------------- helpers ----------------
__device__ __forceinline__ unsigned long long pk2(float a, float b) {
    unsigned long long r;
    asm("mov.b64 %0, {%1,%2};" : "=l"(r) : "f"(a), "f"(b));
    return r;
}
__device__ __forceinline__ void upk2(unsigned long long v, float& a, float& b) {
    asm("mov.b64 {%0,%1}, %2;" : "=f"(a), "=f"(b) : "l"(v));
}
#define FMA2(acc, a, b) asm("fma.rn.f32x2 %0, %1, %2, %0;" : "+l"(acc) : "l"(a), "l"(b))

__device__ __forceinline__ unsigned smem_u32(const void* p) {
    return (unsigned)__cvta_generic_to_shared(p);
}
__device__ __forceinline__ void cp16(unsigned dst, const void* src) {
    asm volatile("cp.async.cg.shared.global [%0], [%1], 16;" :: "r"(dst), "l"(src) : "memory");
}

// ============ k_head1: w, r1, rv — block per r; zero WxT/cst ============
__global__ void __launch_bounds__(256) k_head1(
    const float* __restrict__ pref,
    const float* __restrict__ wm1_w, const float* __restrict__ wm1_b,
    const float* __restrict__ wm2_w, const float* __restrict__ wm2_b,
    const float* __restrict__ ray0_w, const float* __restrict__ ray0_b,
    const float* __restrict__ ray2_w, const float* __restrict__ ray2_b) {
    int r = blockIdx.x;
    int t = threadIdx.x;
    int warp = t >> 5, lane = t & 31;
    __shared__ float sh[16];
    __shared__ float sw[C_];
    __shared__ float sinv;
    __shared__ float sr1[RH_];
    __shared__ float sb2r[D_];

    // zero g_WxT and g_cst each call (graph replay safe)
    for (int z = r * 256 + t; z < IN_ * R_; z += 16 * 256)
        ((float*)g_WxT)[z] = 0.f;
    if (t < R_ && r == 0) g_cst[t] = 0.f;

    float p0 = __ldg(pref + 2 * r), p1 = __ldg(pref + 2 * r + 1);
    if (t < 16) {
        float a = p0 * __ldg(wm1_w + t * 2) + p1 * __ldg(wm1_w + t * 2 + 1) + __ldg(wm1_b + t);
        sh[t] = a > 0.f ? a : 0.f;
    }
    __syncthreads();
    if (t < C_) {
        float a = __ldg(wm2_b + t);
        #pragma unroll
        for (int j = 0; j < 16; j++) a += sh[j] * __ldg(wm2_w + t * 16 + j);
        sw[t] = 1.f / (1.f + expf(-a));
    }
    __syncthreads();
    if (t == 0) {
        float s = 0.f;
        #pragma unroll
        for (int c = 0; c < C_; c++) s += sw[c];
        sinv = 1.f / s;
    }
    __syncthreads();
    if (t < C_) {
        sw[t] *= sinv;
        g_w[r][t] = sw[t];
    }
    __syncthreads();

    if (t < RH_) {
        float a = 0.f;
        #pragma unroll
        for (int c = 0; c < C_; c++) {
            float2 rw = __ldg((const float2*)(ray0_w + (c * RH_ + t) * 2));
            a += sw[c] * (p0 * rw.x + p1 * rw.y + __ldg(ray0_b + c * RH_ + t));
        }
        sr1[t] = a > 0.f ? a : 0.f;
    } else if (t < 64 + D_) {
        int d = t - 64;
        float b = 0.f;
        #pragma unroll
        for (int c = 0; c < C_; c++) b += sw[c] * __ldg(ray2_b + c * D_ + d);
        sb2r[d] = b;
    }
    __syncthreads();

    float r1a = sr1[lane], r1b = sr1[lane + 32];
    float acc[16];
    #pragma unroll
    for (int oi = 0; oi < 16; oi++) acc[oi] = 0.f;
    #pragma unroll
    for (int c = 0; c < C_; c++) {
        float wc = sw[c];
        #pragma unroll
        for (int oi = 0; oi < 16; oi++) {
            int o = warp * 16 + oi;
            const float* row = ray2_w + ((size_t)(c * D_ + o)) * RH_;
            acc[oi] += wc * (__ldg(row + lane) * r1a + __ldg(row + lane + 32) * r1b);
        }
    }
    #pragma unroll
    for (int oi = 0; oi < 16; oi++) {
        float s = acc[oi];
        #pragma unroll
        for (int off = 16; off > 0; off >>= 1) s += __shfl_down_sync(0xffffffffu, s, off);
        if (lane == 0) g_rv[r][warp * 16 + oi] = s + sb2r[warp * 16 + oi];
    }
}

// ============ k_head2: W2/b1 hypernet, grid (16 r, 8 = kind*4+ochunk) ============
// Block owns 32 o's of one kind for one r. Warp owns 4 o's. kind=0 also fills P.
__global__ void __launch_bounds__(256) k_head2(
    const float* __restrict__ fc2_w, const float* __restrict__ fc2_b,
    const float* __restrict__ b1_w,  const float* __restrict__ b1_b) {
    int r = blockIdx.x;
    int kc = blockIdx.y;
    int kind = kc >> 2, oc = kc & 3;
    const float* Wc = kind ? b1_w : fc2_w;
    const float* bc = kind ? b1_b : fc2_b;
    int t = threadIdx.x;
    int warp = t >> 5, lane = t & 31;
    __shared__ float sw[C_];
    __shared__ __align__(16) float srv[D_];
    __shared__ float sres[32];
    __shared__ float sbias[32];

    if (t < C_) sw[t] = g_w[r][t];
    if (t >= 32 && t < 32 + D_) srv[t - 32] = g_rv[r][t - 32];
    __syncthreads();

    if (t < 32) {
        int o = oc * 32 + t;
        float b = 0.f;
        #pragma unroll
        for (int c = 0; c < C_; c++) b += sw[c] * __ldg(bc + c * HID_ + o);
        sbias[t] = b;
    }

    float4 rv4 = *(const float4*)&srv[lane * 4];
    float acc[4];
    #pragma unroll
    for (int j = 0; j < 4; j++) acc[j] = 0.f;
    int ob = oc * 32 + warp * 4;
    #pragma unroll
    for (int c = 0; c < C_; c++) {
        float wc = sw[c];
        #pragma unroll
        for (int j = 0; j < 4; j++) {
            float4 v = __ldg((const float4*)(Wc + ((size_t)(c * HID_ + ob + j)) * D_) + lane);
            acc[j] += wc * (v.x * rv4.x + v.y * rv4.y + v.z * rv4.z + v.w * rv4.w);
        }
    }
    #pragma unroll
    for (int j = 0; j < 4; j++) {
        float s = acc[j];
        #pragma unroll
        for (int off = 16; off > 0; off >>= 1) s += __shfl_down_sync(0xffffffffu, s, off);
        if (lane == 0) sres[warp * 4 + j] = s;
    }
    __syncthreads();

    if (t < 32) {
        int o = oc * 32 + t;
        float v = sres[t] + sbias[t];
        if (kind) g_b1[r][o] = v; else g_W2[r][o] = v;
        sres[t] = v;
    }
    __syncthreads();
    if (kind == 0) {
        // P[c*128 + o][r] = sw[c] * W2[r][o] for this block's 32 o's
        for (int idx = t; idx < C_ * 32; idx += 256) {
            int c = idx >> 5, hh = idx & 31;
            g_P[c * HID_ + oc * 32 + hh][r] = sw[c] * sres[hh];
        }
    }
}

// ============ k_weff v7: cp.async pipeline, strength-reduced addressing ========
extern __shared__ float dsm_[];
__global__ void __launch_bounds__(256, 2) k_weff(const float* __restrict__ fc1_w,
                                                 const float* __restrict__ fc1_b) {
    float* sP   = dsm_;          // 2560 floats (160 ch x 16 r)
    float* sbuf = dsm_ + 2560;   // STG_ x 4096 floats (4 ch x 8 f x 128 d)
    int seg = blockIdx.y;
    int t = threadIdx.x;
    int warp = t >> 5, lane = t & 31;

    for (int idx = t; idx < CHSEG_ * 16; idx += 256)
        sP[idx] = ((const float*)g_P[seg * CHSEG_])[idx];

    const float4* gbase = (const float4*)fc1_w
        + (size_t)(seg * CHSEG_) * 16384u + (size_t)(blockIdx.x * 8 + warp) * 32u + lane;
    unsigned dstbase = smem_u32(sbuf) + (unsigned)((warp * 32 + lane) * 16);
    const float4* myb = (const float4*)sbuf + (warp * 32 + lane);

    __syncthreads();

    #pragma unroll
    for (int s = 0; s < STG_ - 1; s++) {
        #pragma unroll
        for (int q = 0; q < 4; q++)
            cp16(dstbase + (unsigned)(s * 16384 + q * 4096),
                 gbase + (size_t)(s * 4 + q) * 16384u);
        asm volatile("cp.async.commit_group;" ::: "memory");
    }

    unsigned long long acc[4][8];
    #pragma unroll
    for (int j = 0; j < 4; j++)
        #pragma unroll
        for (int rp = 0; rp < 8; rp++) acc[j][rp] = 0ull;

    const float4* gpre = gbase + (size_t)(STG_ - 1) * 4 * 16384u;
    const ulonglong2* pPtr = (const ulonglong2*)sP;

    #pragma unroll 1
    for (int g = 0; g < (CHSEG_ / 4) / STG_; g++) {
        #pragma unroll
        for (int j5 = 0; j5 < STG_; j5++) {
            int i = g * STG_ + j5;
            asm volatile("cp.async.wait_group %0;" :: "n"(STG_ - 2) : "memory");
            const float4* bq = myb + j5 * 1024;
            #pragma unroll
            for (int q = 0; q < 4; q++) {
                float4 v = bq[q * 256];
                ulonglong2 pA = pPtr[q * 4 + 0], pB = pPtr[q * 4 + 1];
                ulonglong2 pC = pPtr[q * 4 + 2], pD = pPtr[q * 4 + 3];
                unsigned long long u0 = pk2(v.x, v.x);
                unsigned long long u1 = pk2(v.y, v.y);
                unsigned long long u2 = pk2(v.z, v.z);
                unsigned long long u3 = pk2(v.w, v.w);
                FMA2(acc[0][0], u0, pA.x); FMA2(acc[0][1], u0, pA.y);
                FMA2(acc[0][2], u0, pB.x); FMA2(acc[0][3], u0, pB.y);
                FMA2(acc[0][4], u0, pC.x); FMA2(acc[0][5], u0, pC.y);
                FMA2(acc[0][6], u0, pD.x); FMA2(acc[0][7], u0, pD.y);
                FMA2(acc[1][0], u1, pA.x); FMA2(acc[1][1], u1, pA.y);
                FMA2(acc[1][2], u1, pB.x); FMA2(acc[1][3], u1, pB.y);
                FMA2(acc[1][4], u1, pC.x); FMA2(acc[1][5], u1, pC.y);
                FMA2(acc[1][6], u1, pD.x); FMA2(acc[1][7], u1, pD.y);
                FMA2(acc[2][0], u2, pA.x); FMA2(acc[2][1], u2, pA.y);
                FMA2(acc[2][2], u2, pB.x); FMA2(acc[2][3], u2, pB.y);
                FMA2(acc[2][4], u2, pC.x); FMA2(acc[2][5], u2, pC.y);
                FMA2(acc[2][6], u2, pD.x); FMA2(acc[2][7], u2, pD.y);
                FMA2(acc[3][0], u3, pA.x); FMA2(acc[3][1], u3, pA.y);
                FMA2(acc[3][2], u3, pB.x); FMA2(acc[3][3], u3, pB.y);
                FMA2(acc[3][4], u3, pC.x); FMA2(acc[3][5], u3, pC.y);
                FMA2(acc[3][6], u3, pD.x); FMA2(acc[3][7], u3, pD.y);
            }
            pPtr += 16;
            if (i < (CHSEG_ / 4) - (STG_ - 1)) {
                const unsigned pslot = (unsigned)(((j5 + STG_ - 1) % STG_) * 16384);
                #pragma unroll
                for (int q = 0; q < 4; q++)
                    cp16(dstbase + pslot + (unsigned)(q * 4096), gpre + q * 16384);
            }
            gpre += 65536;
            asm volatile("cp.async.commit_group;" ::: "memory");
        }
    }
    asm volatile("cp.async.wait_group 0;" ::: "memory");

    int f = blockIdx.x * 8 + warp;
    unsigned long long bacc[8];
    #pragma unroll
    for (int rp = 0; rp < 8; rp++) bacc[rp] = 0ull;
    #pragma unroll
    for (int it = 0; it < CHSEG_ / 32; it++) {
        int chl = it * 32 + lane;
        float bv = __ldg(fc1_b + (size_t)(seg * CHSEG_ + chl) * 512u + f);
        unsigned long long vv = pk2(bv, bv);
        const ulonglong2* pp = (const ulonglong2*)(sP + chl * 16);
        ulonglong2 pA = pp[0], pB = pp[1], pC = pp[2], pD = pp[3];
        FMA2(bacc[0], vv, pA.x); FMA2(bacc[1], vv, pA.y);
        FMA2(bacc[2], vv, pB.x); FMA2(bacc[3], vv, pB.y);
        FMA2(bacc[4], vv, pC.x); FMA2(bacc[5], vv, pC.y);
        FMA2(bacc[6], vv, pD.x); FMA2(bacc[7], vv, pD.y);
    }

    int d0 = lane * 4;
    float accr[16];
    #pragma unroll
    for (int rp = 0; rp < 8; rp++) {
        float a0, a1; upk2(bacc[rp], a0, a1);
        accr[2 * rp] = a0; accr[2 * rp + 1] = a1;
    }
    #pragma unroll
    for (int j = 0; j < 4; j++) {
        #pragma unroll
        for (int rp = 0; rp < 8; rp++) {
            float a0, a1; upk2(acc[j][rp], a0, a1);
            accr[2 * rp]     += a0 * g_rv[2 * rp][d0 + j];
            accr[2 * rp + 1] += a1 * g_rv[2 * rp + 1][d0 + j];
        }
    }
    #pragma unroll
    for (int off = 16; off > 0; off >>= 1)
        #pragma unroll
        for (int r = 0; r < 16; r++)
            accr[r] += __shfl_down_sync(0xffffffffu, accr[r], off);
    if (lane == 0) {
        #pragma unroll
        for (int r = 0; r < 16; r++) g_WeffP[seg][r][f] = accr[r];
    }
}

// ============ k_wx: sum 8 planes -> fold base_w -> atomic Wx; cst+beff ========
__global__ void __launch_bounds__(128) k_wx(const float* __restrict__ base_w,
                                            const float* __restrict__ base_b,
                                            const float* __restrict__ b2_w,
                                            const float* __restrict__ b2_b) {
    __shared__ __align__(16) float sW[32][16];
    int t = threadIdx.x;
    int warp = t >> 5, lane = t & 31;
    int f0 = blockIdx.y * 32;
    for (int idx = t; idx < 32 * 16; idx += 128) {
        int ff = idx >> 4, r = idx & 15;
        float s = 0.f;
        #pragma unroll
        for (int sg = 0; sg < NSEG_; sg++) s += g_WeffP[sg][r][f0 + ff];
        sW[ff][r] = s;
    }
    __syncthreads();
    if (blockIdx.x == 0) {
        int r = t >> 3, fq = (t & 7) * 4;
        float p = 0.f;
        #pragma unroll
        for (int j = 0; j < 4; j++) p += sW[fq + j][r] * __ldg(base_b + f0 + fq + j);
        atomicAdd(&g_cst[r], p);
        if (blockIdx.y == 0) {
            // beff: 4 warps x 4 r each
            #pragma unroll
            for (int q = 0; q < 4; q++) {
                int rr = warp * 4 + q;
                float4 rv4 = *(const float4*)&g_rv[rr][lane * 4];
                float acc = 0.f;
                #pragma unroll
                for (int c = 0; c < C_; c++) {
                    float wc = g_w[rr][c];
                    float4 bw = __ldg((const float4*)(b2_w + c * D_) + lane);
                    acc += wc * (bw.x * rv4.x + bw.y * rv4.y + bw.z * rv4.z + bw.w * rv4.w);
                    if (lane == 0) acc += wc * __ldg(b2_b + c);
                }
                float4 w24 = *(const float4*)&g_W2[rr][lane * 4];
                float4 b14 = *(const float4*)&g_b1[rr][lane * 4];
                acc += w24.x * b14.x + w24.y * b14.y + w24.z * b14.z + w24.w * b14.w;
                #pragma unroll
                for (int off = 16; off > 0; off >>= 1)
                    acc += __shfl_down_sync(0xffffffffu, acc, off);
                if (lane == 0) g_beff[rr] = acc;
            }
        }
    }
    int i = blockIdx.x * 128 + t;
    unsigned long long acc[8];
    #pragma unroll
    for (int rp = 0; rp < 8; rp++) acc[rp] = 0ull;
    #pragma unroll 4
    for (int ff = 0; ff < 32; ff++) {
        float bw = __ldg(base_w + (size_t)(f0 + ff) * IN_ + i);
        unsigned long long b2 = pk2(bw, bw);
        const unsigned long long* pw = (const unsigned long long*)sW[ff];
        #pragma unroll
        for (int rp = 0; rp < 8; rp++) {
            unsigned long long tt = pw[rp];
            FMA2(acc[rp], b2, tt);
        }
    }
    #pragma unroll
    for (int rp = 0; rp < 8; rp++) {
        float a, b; upk2(acc[rp], a, b);
        atomicAdd(&g_WxT[i][2 * rp], a);
        atomicAdd(&g_WxT[i][2 * rp + 1], b);
    }
}

// ============ k_out v7: 512 thr, double-buffered sx/swt, 1 sync per chunk =====
extern __shared__ float osm_[];
__global__ void __launch_bounds__(512) k_out(const float* __restrict__ x,
                                             float* __restrict__ out, int write_raw) {
    float* sxa  = osm_;                         // [16][257]
    float* sxb  = sxa + 16 * 257;
    float* swta = sxb + 16 * 257;               // [256*16]
    float* swtb = swta + 256 * 16;
    float* sp   = swtb + 256 * 16;              // [32*16*17]
    int t = threadIdx.x;
    int bl = t & 15, part = t >> 4;
    int bbase = blockIdx.x * 16;

    int sb = t >> 8, si = t & 255;
    const float* xrow0 = x + (size_t)(bbase + sb) * IN_ + si;
    const float4* wsrc = (const float4*)g_WxT + t;

    #pragma unroll
    for (int k = 0; k < 8; k++)
        sxa[(sb + 2 * k) * 257 + si] = __ldg(xrow0 + (size_t)(2 * k) * IN_);
    #pragma unroll
    for (int k = 0; k < 2; k++)
        ((float4*)swta)[k * 512 + t] = __ldg(wsrc + k * 512);
    __syncthreads();

    unsigned long long acc[8];
    #pragma unroll
    for (int rp = 0; rp < 8; rp++) acc[rp] = 0ull;

    #pragma unroll
    for (int c = 0; c < 4; c++) {
        const float* cx = (c & 1) ? sxb : sxa;
        const float* cw = (c & 1) ? swtb : swta;
        if (c < 3) {
            float* nx = (c & 1) ? sxa : sxb;
            float* nw = (c & 1) ? swta : swtb;
            const float* xs = xrow0 + (c + 1) * 256;
            #pragma unroll
            for (int k = 0; k < 8; k++)
                nx[(sb + 2 * k) * 257 + si] = __ldg(xs + (size_t)(2 * k) * IN_);
            const float4* ws = wsrc + (c + 1) * 1024;
            #pragma unroll
            for (int k = 0; k < 2; k++)
                ((float4*)nw)[k * 512 + t] = __ldg(ws + k * 512);
        }
        const float* xp = cx + bl * 257 + part * 8;
        const ulonglong2* wp = (const ulonglong2*)(cw + part * 128);
        #pragma unroll
        for (int ii = 0; ii < 8; ii++) {
            float xv = xp[ii];
            unsigned long long ux = pk2(xv, xv);
            ulonglong2 wA = wp[0], wB = wp[1], wC = wp[2], wD = wp[3];
            wp += 4;
            FMA2(acc[0], ux, wA.x); FMA2(acc[1], ux, wA.y);
            FMA2(acc[2], ux, wB.x); FMA2(acc[3], ux, wB.y);
            FMA2(acc[4], ux, wC.x); FMA2(acc[5], ux, wC.y);
            FMA2(acc[6], ux, wD.x); FMA2(acc[7], ux, wD.y);
        }
        __syncthreads();
    }

    float* myp = sp + (size_t)(part * 16 + bl) * 17;
    #pragma unroll
    for (int rp = 0; rp < 8; rp++) {
        float a, b; upk2(acc[rp], a, b);
        myp[2 * rp] = a;
        myp[2 * rp + 1] = b;
    }
    __syncthreads();

    if (t < 256) {
        int r = t >> 4, b = t & 15;
        float s = 0.f;
        #pragma unroll
        for (int p = 0; p < 32; p++) s += sp[(size_t)(p * 16 + b) * 17 + r];
        float v = s + g_cst[r] + g_beff[r];
        out[r * B_ + bbase + b] = 1.f / (1.f + expf(-v));
        if (write_raw) out[R_ * B_ + r * B_ + bbase + b] = v;
    }
}

// ---------------- launcher ----------------
extern "C" void kernel_launch(void* const* d_in, const int* in_sizes, int n_in,
                              void* d_out, int out_size) {
    const float* x      = (const float*)d_in[0];
    const float* pref   = (const float*)d_in[1];
    const float* base_w = (const float*)d_in[2];
    const float* base_b = (const float*)d_in[3];
    const float* wm1_w  = (const float*)d_in[4];
    const float* wm1_b  = (const float*)d_in[5];
    const float* wm2_w  = (const float*)d_in[6];
    const float* wm2_b  = (const float*)d_in[7];
    const float* ray0_w = (const float*)d_in[8];
    const float* ray0_b = (const float*)d_in[9];
    const float* ray2_w = (const float*)d_in[10];
    const float* ray2_b = (const float*)d_in[11];
    const float* fc1_w  = (const float*)d_in[12];
    const float* fc1_b  = (const float*)d_in[13];
    const float* b1_w   = (const float*)d_in[14];
    const float* b1_b   = (const float*)d_in[15];
    const float* fc2_w  = (const float*)d_in[16];
    const float* fc2_b  = (const float*)d_in[17];
    const float* b2_w   = (const float*)d_in[18];
    const float* b2_b   = (const float*)d_in[19];
    float* out = (float*)d_out;
    int write_raw = (out_size >= 2 * R_ * B_) ? 1 : 0;

    cudaFuncSetAttribute(k_weff, cudaFuncAttributeMaxDynamicSharedMemorySize, KW_SMEM_);
    cudaFuncSetAttribute(k_out, cudaFuncAttributeMaxDynamicSharedMemorySize, KO_SMEM_);

    k_head1<<<R_, 256>>>(pref, wm1_w, wm1_b, wm2_w, wm2_b,
                         ray0_w, ray0_b, ray2_w, ray2_b);
    k_head2<<<dim3(R_, 8), 256>>>(fc2_w, fc2_b, b1_w, b1_b);
    k_weff<<<dim3(F_ / 8, NSEG_), 256, KW_SMEM_>>>(fc1_w, fc1_b);
    k_wx<<<dim3(8, 16), 128>>>(base_w, base_b, b2_w, b2_b);   // #4 -> profiled
    k_out<<<B_ / 16, 512, KO_SMEM_>>>(x, out, write_raw);
}

// round 17
// speedup vs baseline: 1.1660x; 1.0296x over previous
#include <cuda_runtime.h>
#include <cmath>

// Problem constants
#define B_    4096
#define IN_   1024
#define F_    512
#define HID_  128
#define D_    128
#define RH_   64
#define C_    10
#define R_    16
#define CH_   1280   // C_*HID_
#define NSEG_ 8
#define CHSEG_ 160   // CH_/NSEG_
#define STG_  5      // cp.async pipeline stages
#define KW_SMEM_ ((2560 + STG_ * 4096) * 4)   // 92160 bytes
#define KO_SMEM_ ((2 * 16 * 257 + 2 * 256 * 16 + 32 * 16 * 17) * 4)  // 101504 bytes

// ---------------- device scratch ----------------
__device__ __align__(256) float g_w[R_][C_];
__device__ __align__(256) float g_rv[R_][D_];
__device__ __align__(256) float g_W2[R_][HID_];
__device__ __align__(256) float g_b1[R_][HID_];
__device__ __align__(256) float g_beff[R_];
__device__ __align__(256) float g_P[CH_][R_];            // P[ch][r] = w[r,c]*W2[r,h]
__device__ __align__(256) float g_WeffP[NSEG_][R_][F_];  // k_weff partials (incl. bias)
__device__ __align__(256) float g_WxT[IN_][R_];          // [i][r], atomic-accumulated
__device__ __align__(256) float g_cst[R_];               // Weff·base_b (atomics)

// ---------------- helpers ----------------
__device__ __forceinline__ unsigned long long pk2(float a, float b) {
    unsigned long long r;
    asm("mov.b64 %0, {%1,%2};" : "=l"(r) : "f"(a), "f"(b));
    return r;
}
__device__ __forceinline__ void upk2(unsigned long long v, float& a, float& b) {
    asm("mov.b64 {%0,%1}, %2;" : "=f"(a), "=f"(b) : "l"(v));
}
#define FMA2(acc, a, b) asm("fma.rn.f32x2 %0, %1, %2, %0;" : "+l"(acc) : "l"(a), "l"(b))

__device__ __forceinline__ unsigned smem_u32(const void* p) {
    return (unsigned)__cvta_generic_to_shared(p);
}
__device__ __forceinline__ void cp16(unsigned dst, const void* src) {
    asm volatile("cp.async.cg.shared.global [%0], [%1], 16;" :: "r"(dst), "l"(src) : "memory");
}

// ============ k_head1: w, r1, rv — block per r; zero WxT/cst ============
__global__ void __launch_bounds__(256) k_head1(
    const float* __restrict__ pref,
    const float* __restrict__ wm1_w, const float* __restrict__ wm1_b,
    const float* __restrict__ wm2_w, const float* __restrict__ wm2_b,
    const float* __restrict__ ray0_w, const float* __restrict__ ray0_b,
    const float* __restrict__ ray2_w, const float* __restrict__ ray2_b) {
    int r = blockIdx.x;
    int t = threadIdx.x;
    int warp = t >> 5, lane = t & 31;
    __shared__ float sh[16];
    __shared__ float sw[C_];
    __shared__ float sinv;
    __shared__ float sr1[RH_];
    __shared__ float sb2r[D_];

    // zero g_WxT and g_cst each call (graph replay safe)
    for (int z = r * 256 + t; z < IN_ * R_; z += 16 * 256)
        ((float*)g_WxT)[z] = 0.f;
    if (t < R_ && r == 0) g_cst[t] = 0.f;

    float p0 = __ldg(pref + 2 * r), p1 = __ldg(pref + 2 * r + 1);
    if (t < 16) {
        float a = p0 * __ldg(wm1_w + t * 2) + p1 * __ldg(wm1_w + t * 2 + 1) + __ldg(wm1_b + t);
        sh[t] = a > 0.f ? a : 0.f;
    }
    __syncthreads();
    if (t < C_) {
        float a = __ldg(wm2_b + t);
        #pragma unroll
        for (int j = 0; j < 16; j++) a += sh[j] * __ldg(wm2_w + t * 16 + j);
        sw[t] = 1.f / (1.f + expf(-a));
    }
    __syncthreads();
    if (t == 0) {
        float s = 0.f;
        #pragma unroll
        for (int c = 0; c < C_; c++) s += sw[c];
        sinv = 1.f / s;
    }
    __syncthreads();
    if (t < C_) {
        sw[t] *= sinv;
        g_w[r][t] = sw[t];
    }
    __syncthreads();

    if (t < RH_) {
        float a = 0.f;
        #pragma unroll
        for (int c = 0; c < C_; c++) {
            float2 rw = __ldg((const float2*)(ray0_w + (c * RH_ + t) * 2));
            a += sw[c] * (p0 * rw.x + p1 * rw.y + __ldg(ray0_b + c * RH_ + t));
        }
        sr1[t] = a > 0.f ? a : 0.f;
    } else if (t < 64 + D_) {
        int d = t - 64;
        float b = 0.f;
        #pragma unroll
        for (int c = 0; c < C_; c++) b += sw[c] * __ldg(ray2_b + c * D_ + d);
        sb2r[d] = b;
    }
    __syncthreads();

    float r1a = sr1[lane], r1b = sr1[lane + 32];
    float acc[16];
    #pragma unroll
    for (int oi = 0; oi < 16; oi++) acc[oi] = 0.f;
    #pragma unroll
    for (int c = 0; c < C_; c++) {
        float wc = sw[c];
        #pragma unroll
        for (int oi = 0; oi < 16; oi++) {
            int o = warp * 16 + oi;
            const float* row = ray2_w + ((size_t)(c * D_ + o)) * RH_;
            acc[oi] += wc * (__ldg(row + lane) * r1a + __ldg(row + lane + 32) * r1b);
        }
    }
    #pragma unroll
    for (int oi = 0; oi < 16; oi++) {
        float s = acc[oi];
        #pragma unroll
        for (int off = 16; off > 0; off >>= 1) s += __shfl_down_sync(0xffffffffu, s, off);
        if (lane == 0) g_rv[r][warp * 16 + oi] = s + sb2r[warp * 16 + oi];
    }
}

// ============ k_head2: W2/b1 hypernet, grid (16 r, 8 = kind*4+ochunk) ============
__global__ void __launch_bounds__(256) k_head2(
    const float* __restrict__ fc2_w, const float* __restrict__ fc2_b,
    const float* __restrict__ b1_w,  const float* __restrict__ b1_b) {
    int r = blockIdx.x;
    int kc = blockIdx.y;
    int kind = kc >> 2, oc = kc & 3;
    const float* Wc = kind ? b1_w : fc2_w;
    const float* bc = kind ? b1_b : fc2_b;
    int t = threadIdx.x;
    int warp = t >> 5, lane = t & 31;
    __shared__ float sw[C_];
    __shared__ __align__(16) float srv[D_];
    __shared__ float sres[32];
    __shared__ float sbias[32];

    if (t < C_) sw[t] = g_w[r][t];
    if (t >= 32 && t < 32 + D_) srv[t - 32] = g_rv[r][t - 32];
    __syncthreads();

    if (t < 32) {
        int o = oc * 32 + t;
        float b = 0.f;
        #pragma unroll
        for (int c = 0; c < C_; c++) b += sw[c] * __ldg(bc + c * HID_ + o);
        sbias[t] = b;
    }

    float4 rv4 = *(const float4*)&srv[lane * 4];
    float acc[4];
    #pragma unroll
    for (int j = 0; j < 4; j++) acc[j] = 0.f;
    int ob = oc * 32 + warp * 4;
    #pragma unroll
    for (int c = 0; c < C_; c++) {
        float wc = sw[c];
        #pragma unroll
        for (int j = 0; j < 4; j++) {
            float4 v = __ldg((const float4*)(Wc + ((size_t)(c * HID_ + ob + j)) * D_) + lane);
            acc[j] += wc * (v.x * rv4.x + v.y * rv4.y + v.z * rv4.z + v.w * rv4.w);
        }
    }
    #pragma unroll
    for (int j = 0; j < 4; j++) {
        float s = acc[j];
        #pragma unroll
        for (int off = 16; off > 0; off >>= 1) s += __shfl_down_sync(0xffffffffu, s, off);
        if (lane == 0) sres[warp * 4 + j] = s;
    }
    __syncthreads();

    if (t < 32) {
        int o = oc * 32 + t;
        float v = sres[t] + sbias[t];
        if (kind) g_b1[r][o] = v; else g_W2[r][o] = v;
        sres[t] = v;
    }
    __syncthreads();
    if (kind == 0) {
        for (int idx = t; idx < C_ * 32; idx += 256) {
            int c = idx >> 5, hh = idx & 31;
            g_P[c * HID_ + oc * 32 + hh][r] = sw[c] * sres[hh];
        }
    }
}

// ============ k_weff v7: cp.async pipeline, strength-reduced addressing ========
extern __shared__ float dsm_[];
__global__ void __launch_bounds__(256, 2) k_weff(const float* __restrict__ fc1_w,
                                                 const float* __restrict__ fc1_b) {
    float* sP   = dsm_;          // 2560 floats (160 ch x 16 r)
    float* sbuf = dsm_ + 2560;   // STG_ x 4096 floats
    int seg = blockIdx.y;
    int t = threadIdx.x;
    int warp = t >> 5, lane = t & 31;

    for (int idx = t; idx < CHSEG_ * 16; idx += 256)
        sP[idx] = ((const float*)g_P[seg * CHSEG_])[idx];

    const float4* gbase = (const float4*)fc1_w
        + (size_t)(seg * CHSEG_) * 16384u + (size_t)(blockIdx.x * 8 + warp) * 32u + lane;
    unsigned dstbase = smem_u32(sbuf) + (unsigned)((warp * 32 + lane) * 16);
    const float4* myb = (const float4*)sbuf + (warp * 32 + lane);

    __syncthreads();

    #pragma unroll
    for (int s = 0; s < STG_ - 1; s++) {
        #pragma unroll
        for (int q = 0; q < 4; q++)
            cp16(dstbase + (unsigned)(s * 16384 + q * 4096),
                 gbase + (size_t)(s * 4 + q) * 16384u);
        asm volatile("cp.async.commit_group;" ::: "memory");
    }

    unsigned long long acc[4][8];
    #pragma unroll
    for (int j = 0; j < 4; j++)
        #pragma unroll
        for (int rp = 0; rp < 8; rp++) acc[j][rp] = 0ull;

    const float4* gpre = gbase + (size_t)(STG_ - 1) * 4 * 16384u;
    const ulonglong2* pPtr = (const ulonglong2*)sP;

    #pragma unroll 1
    for (int g = 0; g < (CHSEG_ / 4) / STG_; g++) {
        #pragma unroll
        for (int j5 = 0; j5 < STG_; j5++) {
            int i = g * STG_ + j5;
            asm volatile("cp.async.wait_group %0;" :: "n"(STG_ - 2) : "memory");
            const float4* bq = myb + j5 * 1024;
            #pragma unroll
            for (int q = 0; q < 4; q++) {
                float4 v = bq[q * 256];
                ulonglong2 pA = pPtr[q * 4 + 0], pB = pPtr[q * 4 + 1];
                ulonglong2 pC = pPtr[q * 4 + 2], pD = pPtr[q * 4 + 3];
                unsigned long long u0 = pk2(v.x, v.x);
                unsigned long long u1 = pk2(v.y, v.y);
                unsigned long long u2 = pk2(v.z, v.z);
                unsigned long long u3 = pk2(v.w, v.w);
                FMA2(acc[0][0], u0, pA.x); FMA2(acc[0][1], u0, pA.y);
                FMA2(acc[0][2], u0, pB.x); FMA2(acc[0][3], u0, pB.y);
                FMA2(acc[0][4], u0, pC.x); FMA2(acc[0][5], u0, pC.y);
                FMA2(acc[0][6], u0, pD.x); FMA2(acc[0][7], u0, pD.y);
                FMA2(acc[1][0], u1, pA.x); FMA2(acc[1][1], u1, pA.y);
                FMA2(acc[1][2], u1, pB.x); FMA2(acc[1][3], u1, pB.y);
                FMA2(acc[1][4], u1, pC.x); FMA2(acc[1][5], u1, pC.y);
                FMA2(acc[1][6], u1, pD.x); FMA2(acc[1][7], u1, pD.y);
                FMA2(acc[2][0], u2, pA.x); FMA2(acc[2][1], u2, pA.y);
                FMA2(acc[2][2], u2, pB.x); FMA2(acc[2][3], u2, pB.y);
                FMA2(acc[2][4], u2, pC.x); FMA2(acc[2][5], u2, pC.y);
                FMA2(acc[2][6], u2, pD.x); FMA2(acc[2][7], u2, pD.y);
                FMA2(acc[3][0], u3, pA.x); FMA2(acc[3][1], u3, pA.y);
                FMA2(acc[3][2], u3, pB.x); FMA2(acc[3][3], u3, pB.y);
                FMA2(acc[3][4], u3, pC.x); FMA2(acc[3][5], u3, pC.y);
                FMA2(acc[3][6], u3, pD.x); FMA2(acc[3][7], u3, pD.y);
            }
            pPtr += 16;
            if (i < (CHSEG_ / 4) - (STG_ - 1)) {
                const unsigned pslot = (unsigned)(((j5 + STG_ - 1) % STG_) * 16384);
                #pragma unroll
                for (int q = 0; q < 4; q++)
                    cp16(dstbase + pslot + (unsigned)(q * 4096), gpre + q * 16384);
            }
            gpre += 65536;
            asm volatile("cp.async.commit_group;" ::: "memory");
        }
    }
    asm volatile("cp.async.wait_group 0;" ::: "memory");

    int f = blockIdx.x * 8 + warp;
    unsigned long long bacc[8];
    #pragma unroll
    for (int rp = 0; rp < 8; rp++) bacc[rp] = 0ull;
    #pragma unroll
    for (int it = 0; it < CHSEG_ / 32; it++) {
        int chl = it * 32 + lane;
        float bv = __ldg(fc1_b + (size_t)(seg * CHSEG_ + chl) * 512u + f);
        unsigned long long vv = pk2(bv, bv);
        const ulonglong2* pp = (const ulonglong2*)(sP + chl * 16);
        ulonglong2 pA = pp[0], pB = pp[1], pC = pp[2], pD = pp[3];
        FMA2(bacc[0], vv, pA.x); FMA2(bacc[1], vv, pA.y);
        FMA2(bacc[2], vv, pB.x); FMA2(bacc[3], vv, pB.y);
        FMA2(bacc[4], vv, pC.x); FMA2(bacc[5], vv, pC.y);
        FMA2(bacc[6], vv, pD.x); FMA2(bacc[7], vv, pD.y);
    }

    int d0 = lane * 4;
    float accr[16];
    #pragma unroll
    for (int rp = 0; rp < 8; rp++) {
        float a0, a1; upk2(bacc[rp], a0, a1);
        accr[2 * rp] = a0; accr[2 * rp + 1] = a1;
    }
    #pragma unroll
    for (int j = 0; j < 4; j++) {
        #pragma unroll
        for (int rp = 0; rp < 8; rp++) {
            float a0, a1; upk2(acc[j][rp], a0, a1);
            accr[2 * rp]     += a0 * g_rv[2 * rp][d0 + j];
            accr[2 * rp + 1] += a1 * g_rv[2 * rp + 1][d0 + j];
        }
    }
    #pragma unroll
    for (int off = 16; off > 0; off >>= 1)
        #pragma unroll
        for (int r = 0; r < 16; r++)
            accr[r] += __shfl_down_sync(0xffffffffu, accr[r], off);
    if (lane == 0) {
        #pragma unroll
        for (int r = 0; r < 16; r++) g_WeffP[seg][r][f] = accr[r];
    }
}

// ============ k_wx v2: 16 ff per block, grid (8, 32); full-unroll LDG batch ====
__global__ void __launch_bounds__(128) k_wx(const float* __restrict__ base_w,
                                            const float* __restrict__ base_b,
                                            const float* __restrict__ b2_w,
                                            const float* __restrict__ b2_b) {
    __shared__ __align__(16) float sW[16][16];
    int t = threadIdx.x;
    int warp = t >> 5, lane = t & 31;
    int f0 = blockIdx.y * 16;
    for (int idx = t; idx < 16 * 16; idx += 128) {
        int ff = idx >> 4, r = idx & 15;
        float s = 0.f;
        #pragma unroll
        for (int sg = 0; sg < NSEG_; sg++) s += g_WeffP[sg][r][f0 + ff];
        sW[ff][r] = s;
    }
    __syncthreads();
    if (blockIdx.x == 0) {
        if (t < 128) {
            int r = t >> 3, fq = (t & 7) * 2;
            float p = sW[fq][r] * __ldg(base_b + f0 + fq)
                    + sW[fq + 1][r] * __ldg(base_b + f0 + fq + 1);
            atomicAdd(&g_cst[r], p);
        }
        if (blockIdx.y == 0) {
            // beff: 4 warps x 4 r each
            #pragma unroll
            for (int q = 0; q < 4; q++) {
                int rr = warp * 4 + q;
                float4 rv4 = *(const float4*)&g_rv[rr][lane * 4];
                float acc = 0.f;
                #pragma unroll
                for (int c = 0; c < C_; c++) {
                    float wc = g_w[rr][c];
                    float4 bw = __ldg((const float4*)(b2_w + c * D_) + lane);
                    acc += wc * (bw.x * rv4.x + bw.y * rv4.y + bw.z * rv4.z + bw.w * rv4.w);
                    if (lane == 0) acc += wc * __ldg(b2_b + c);
                }
                float4 w24 = *(const float4*)&g_W2[rr][lane * 4];
                float4 b14 = *(const float4*)&g_b1[rr][lane * 4];
                acc += w24.x * b14.x + w24.y * b14.y + w24.z * b14.z + w24.w * b14.w;
                #pragma unroll
                for (int off = 16; off > 0; off >>= 1)
                    acc += __shfl_down_sync(0xffffffffu, acc, off);
                if (lane == 0) g_beff[rr] = acc;
            }
        }
    }
    int i = blockIdx.x * 128 + t;
    // batch all 16 base_w loads (independent, 4KB stride) for max MLP
    float bw[16];
    #pragma unroll
    for (int ff = 0; ff < 16; ff++)
        bw[ff] = __ldg(base_w + (size_t)(f0 + ff) * IN_ + i);
    unsigned long long acc[8];
    #pragma unroll
    for (int rp = 0; rp < 8; rp++) acc[rp] = 0ull;
    #pragma unroll
    for (int ff = 0; ff < 16; ff++) {
        unsigned long long b2 = pk2(bw[ff], bw[ff]);
        const unsigned long long* pw = (const unsigned long long*)sW[ff];
        #pragma unroll
        for (int rp = 0; rp < 8; rp++) {
            unsigned long long tt = pw[rp];
            FMA2(acc[rp], b2, tt);
        }
    }
    #pragma unroll
    for (int rp = 0; rp < 8; rp++) {
        float a, b; upk2(acc[rp], a, b);
        atomicAdd(&g_WxT[i][2 * rp], a);
        atomicAdd(&g_WxT[i][2 * rp + 1], b);
    }
}

// ============ k_out v7: 512 thr, double-buffered sx/swt, 1 sync per chunk =====
extern __shared__ float osm_[];
__global__ void __launch_bounds__(512) k_out(const float* __restrict__ x,
                                             float* __restrict__ out, int write_raw) {
    float* sxa  = osm_;                         // [16][257]
    float* sxb  = sxa + 16 * 257;
    float* swta = sxb + 16 * 257;               // [256*16]
    float* swtb = swta + 256 * 16;
    float* sp   = swtb + 256 * 16;              // [32*16*17]
    int t = threadIdx.x;
    int bl = t & 15, part = t >> 4;
    int bbase = blockIdx.x * 16;

    int sb = t >> 8, si = t & 255;
    const float* xrow0 = x + (size_t)(bbase + sb) * IN_ + si;
    const float4* wsrc = (const float4*)g_WxT + t;

    #pragma unroll
    for (int k = 0; k < 8; k++)
        sxa[(sb + 2 * k) * 257 + si] = __ldg(xrow0 + (size_t)(2 * k) * IN_);
    #pragma unroll
    for (int k = 0; k < 2; k++)
        ((float4*)swta)[k * 512 + t] = __ldg(wsrc + k * 512);
    __syncthreads();

    unsigned long long acc[8];
    #pragma unroll
    for (int rp = 0; rp < 8; rp++) acc[rp] = 0ull;

    #pragma unroll
    for (int c = 0; c < 4; c++) {
        const float* cx = (c & 1) ? sxb : sxa;
        const float* cw = (c & 1) ? swtb : swta;
        if (c < 3) {
            float* nx = (c & 1) ? sxa : sxb;
            float* nw = (c & 1) ? swta : swtb;
            const float* xs = xrow0 + (c + 1) * 256;
            #pragma unroll
            for (int k = 0; k < 8; k++)
                nx[(sb + 2 * k) * 257 + si] = __ldg(xs + (size_t)(2 * k) * IN_);
            const float4* ws = wsrc + (c + 1) * 1024;
            #pragma unroll
            for (int k = 0; k < 2; k++)
                ((float4*)nw)[k * 512 + t] = __ldg(ws + k * 512);
        }
        const float* xp = cx + bl * 257 + part * 8;
        const ulonglong2* wp = (const ulonglong2*)(cw + part * 128);
        #pragma unroll
        for (int ii = 0; ii < 8; ii++) {
            float xv = xp[ii];
            unsigned long long ux = pk2(xv, xv);
            ulonglong2 wA = wp[0], wB = wp[1], wC = wp[2], wD = wp[3];
            wp += 4;
            FMA2(acc[0], ux, wA.x); FMA2(acc[1], ux, wA.y);
            FMA2(acc[2], ux, wB.x); FMA2(acc[3], ux, wB.y);
            FMA2(acc[4], ux, wC.x); FMA2(acc[5], ux, wC.y);
            FMA2(acc[6], ux, wD.x); FMA2(acc[7], ux, wD.y);
        }
        __syncthreads();
    }

    float* myp = sp + (size_t)(part * 16 + bl) * 17;
    #pragma unroll
    for (int rp = 0; rp < 8; rp++) {
        float a, b; upk2(acc[rp], a, b);
        myp[2 * rp] = a;
        myp[2 * rp + 1] = b;
    }
    __syncthreads();

    if (t < 256) {
        int r = t >> 4, b = t & 15;
        float s = 0.f;
        #pragma unroll
        for (int p = 0; p < 32; p++) s += sp[(size_t)(p * 16 + b) * 17 + r];
        float v = s + g_cst[r] + g_beff[r];
        out[r * B_ + bbase + b] = 1.f / (1.f + expf(-v));
        if (write_raw) out[R_ * B_ + r * B_ + bbase + b] = v;
    }
}

// ---------------- launcher ----------------
extern "C" void kernel_launch(void* const* d_in, const int* in_sizes, int n_in,
                              void* d_out, int out_size) {
    const float* x      = (const float*)d_in[0];
    const float* pref   = (const float*)d_in[1];
    const float* base_w = (const float*)d_in[2];
    const float* base_b = (const float*)d_in[3];
    const float* wm1_w  = (const float*)d_in[4];
    const float* wm1_b  = (const float*)d_in[5];
    const float* wm2_w  = (const float*)d_in[6];
    const float* wm2_b  = (const float*)d_in[7];
    const float* ray0_w = (const float*)d_in[8];
    const float* ray0_b = (const float*)d_in[9];
    const float* ray2_w = (const float*)d_in[10];
    const float* ray2_b = (const float*)d_in[11];
    const float* fc1_w  = (const float*)d_in[12];
    const float* fc1_b  = (const float*)d_in[13];
    const float* b1_w   = (const float*)d_in[14];
    const float* b1_b   = (const float*)d_in[15];
    const float* fc2_w  = (const float*)d_in[16];
    const float* fc2_b  = (const float*)d_in[17];
    const float* b2_w   = (const float*)d_in[18];
    const float* b2_b   = (const float*)d_in[19];
    float* out = (float*)d_out;
    int write_raw = (out_size >= 2 * R_ * B_) ? 1 : 0;

    cudaFuncSetAttribute(k_weff, cudaFuncAttributeMaxDynamicSharedMemorySize, KW_SMEM_);
    cudaFuncSetAttribute(k_out, cudaFuncAttributeMaxDynamicSharedMemorySize, KO_SMEM_);

    k_head1<<<R_, 256>>>(pref, wm1_w, wm1_b, wm2_w, wm2_b,
                         ray0_w, ray0_b, ray2_w, ray2_b);
    k_head2<<<dim3(R_, 8), 256>>>(fc2_w, fc2_b, b1_w, b1_b);
    k_weff<<<dim3(F_ / 8, NSEG_), 256, KW_SMEM_>>>(fc1_w, fc1_b);
    k_wx<<<dim3(8, 32), 128>>>(base_w, base_b, b2_w, b2_b);   // #4 -> profiled
    k_out<<<B_ / 16, 512, KO_SMEM_>>>(x, out, write_raw);
}